// round 1
// baseline (speedup 1.0000x reference)
#include <cuda_runtime.h>
#include <math.h>

// ---------------- problem constants ----------------
#define T_TOK 2048      // BATCH*SEQ
#define HID   8192
#define QKVW  9216      // G*(HQ+2)*HEAD = 8*18*64
#define GKV   8
#define HQ    16
#define HEADD 64
#define SEQ   1024
#define BATCHN 2

// scratch (allocation-free rule: __device__ globals)
__device__ float g_qkv[(size_t)T_TOK * QKVW];   // 75.5 MB
__device__ float g_attn[(size_t)T_TOK * HID];   // 67 MB

// ---------------- SGEMM: C[M,N] = A[M,K] @ B[K,N], all row-major ----------------
#define BM 128
#define BN 128
#define BK 8
#define TM 8
#define TN 8

__global__ __launch_bounds__(256) void sgemm_kernel(
    int M, int N, int K,
    const float* __restrict__ A, const float* __restrict__ B, float* __restrict__ C)
{
    __shared__ float As[BK][BM];   // stored transposed for conflict-free reads
    __shared__ float Bs[BK][BN];

    const int tid  = threadIdx.x;
    const int cRow = blockIdx.y;
    const int cCol = blockIdx.x;

    A += (size_t)cRow * BM * K;
    B += cCol * BN;
    C += (size_t)cRow * BM * N + cCol * BN;

    const int threadCol = tid % (BN / TN);   // 0..15
    const int threadRow = tid / (BN / TN);   // 0..15
    const int innerRowA = tid / (BK / 4);    // 0..127
    const int innerColA = tid % (BK / 4);    // 0..1
    const int innerRowB = tid / (BN / 4);    // 0..7
    const int innerColB = tid % (BN / 4);    // 0..31

    float acc[TM * TN];
    #pragma unroll
    for (int i = 0; i < TM * TN; i++) acc[i] = 0.f;
    float regM[TM], regN[TN];

    for (int k0 = 0; k0 < K; k0 += BK) {
        float4 a4 = *(const float4*)(A + (size_t)innerRowA * K + innerColA * 4);
        As[innerColA * 4 + 0][innerRowA] = a4.x;
        As[innerColA * 4 + 1][innerRowA] = a4.y;
        As[innerColA * 4 + 2][innerRowA] = a4.z;
        As[innerColA * 4 + 3][innerRowA] = a4.w;
        *(float4*)(&Bs[innerRowB][innerColB * 4]) =
            *(const float4*)(B + (size_t)innerRowB * N + innerColB * 4);
        __syncthreads();

        A += BK;
        B += (size_t)BK * N;

        #pragma unroll
        for (int k = 0; k < BK; ++k) {
            #pragma unroll
            for (int i = 0; i < TM; i++) regM[i] = As[k][threadRow * TM + i];
            #pragma unroll
            for (int j = 0; j < TN; j++) regN[j] = Bs[k][threadCol * TN + j];
            #pragma unroll
            for (int i = 0; i < TM; i++)
                #pragma unroll
                for (int j = 0; j < TN; j++)
                    acc[i * TN + j] += regM[i] * regN[j];
        }
        __syncthreads();
    }

    #pragma unroll
    for (int i = 0; i < TM; i++) {
        #pragma unroll
        for (int j = 0; j < TN; j += 4) {
            float4 v;
            v.x = acc[i * TN + j + 0];
            v.y = acc[i * TN + j + 1];
            v.z = acc[i * TN + j + 2];
            v.w = acc[i * TN + j + 3];
            *(float4*)(C + (size_t)(threadRow * TM + i) * N + threadCol * TN + j) = v;
        }
    }
}

// ---------------- RoPE (in-place on qkv): q heads 0..15 and k head (idx 16) ----------------
__global__ __launch_bounds__(256) void rope_kernel(
    float* __restrict__ qkv, const float* __restrict__ cosv, const float* __restrict__ sinv)
{
    int idx = blockIdx.x * 256 + threadIdx.x;
    const int total = T_TOK * GKV * (HQ + 1) * 32;   // 8,912,896
    if (idx >= total) return;
    int pr  = idx & 31;            // rotation pair 0..31
    int tmp = idx >> 5;
    int hd  = tmp % (HQ + 1);      // 0..15 = q heads, 16 = k
    tmp    /= (HQ + 1);
    int g   = tmp & 7;
    int t   = tmp >> 3;

    size_t base = (size_t)t * QKVW + g * ((HQ + 2) * HEADD) + hd * HEADD;
    float c = cosv[t * 32 + pr];
    float s = sinv[t * 32 + pr];
    float x1 = qkv[base + pr];
    float x2 = qkv[base + 32 + pr];
    qkv[base + pr]      = x1 * c - x2 * s;
    qkv[base + 32 + pr] = x2 * c + x1 * s;
}

// ---------------- Flash attention (fp32, online softmax) ----------------
// grid = (16 qblocks, 16 q-heads, 16 (b,g)); block = 256 threads.
// Thread layout: row = tid>>2 (query within 64-tile), cg = tid&3.
// Thread owns key/val columns lc = c*4+cg (c = 0..15) -> all smem access
// patterns with stride AS=68 are bank-conflict-free and float4-aligned.
#define AS 68

__global__ __launch_bounds__(256) void attn_kernel(
    const float* __restrict__ qkv, float* __restrict__ out)
{
    extern __shared__ float sm[];
    float* Qs = sm;
    float* Ks = sm + 64 * AS;
    float* Vs = sm + 2 * 64 * AS;
    float* Ps = sm + 3 * 64 * AS;

    const int qb = blockIdx.x;     // 0..15
    const int h  = blockIdx.y;     // 0..15
    const int bg = blockIdx.z;     // 0..15
    const int b  = bg >> 3, g = bg & 7;
    const int tid = threadIdx.x;
    const int row = tid >> 2;      // 0..63
    const int cg  = tid & 3;

    const int tb   = b * SEQ;
    const int qoff = g * ((HQ + 2) * HEADD) + h * HEADD;
    const int koff = g * ((HQ + 2) * HEADD) + HQ * HEADD;
    const int voff = koff + HEADD;
    const int q0   = qb * 64;

    // load Q tile [64 x 64]
    for (int idx = tid; idx < 64 * 64; idx += 256) {
        int r = idx >> 6, c = idx & 63;
        Qs[r * AS + c] = qkv[(size_t)(tb + q0 + r) * QKVW + qoff + c];
    }

    float acc[16];
    #pragma unroll
    for (int i = 0; i < 16; i++) acc[i] = 0.f;
    float m = -INFINITY, l = 0.f;

    for (int jb = 0; jb <= qb; jb++) {
        const int j0 = jb * 64;
        __syncthreads();   // protect Ks/Vs/Ps from prior iteration readers
        for (int idx = tid; idx < 64 * 64; idx += 256) {
            int r = idx >> 6, c = idx & 63;
            size_t gbase = (size_t)(tb + j0 + r) * QKVW;
            Ks[r * AS + c] = qkv[gbase + koff + c];
            Vs[r * AS + c] = qkv[gbase + voff + c];
        }
        __syncthreads();

        // S = Q K^T for this thread's 16 key columns (float4 over d)
        float s[16];
        #pragma unroll
        for (int c = 0; c < 16; c++) s[c] = 0.f;
        #pragma unroll 4
        for (int d4 = 0; d4 < 16; d4++) {
            float4 q4 = *(const float4*)(Qs + row * AS + d4 * 4);
            #pragma unroll
            for (int c = 0; c < 16; c++) {
                float4 k4 = *(const float4*)(Ks + (c * 4 + cg) * AS + d4 * 4);
                s[c] += q4.x * k4.x + q4.y * k4.y + q4.z * k4.z + q4.w * k4.w;
            }
        }

        const float SCALE = 0.125f;   // 1/sqrt(64)
        float rowmax = -INFINITY;
        if (jb == qb) {
            #pragma unroll
            for (int c = 0; c < 16; c++) {
                int kj = j0 + c * 4 + cg;
                s[c] = (kj <= q0 + row) ? s[c] * SCALE : -INFINITY;
                rowmax = fmaxf(rowmax, s[c]);
            }
        } else {
            #pragma unroll
            for (int c = 0; c < 16; c++) {
                s[c] *= SCALE;
                rowmax = fmaxf(rowmax, s[c]);
            }
        }
        // row reduction across the 4 lanes sharing this row (lanes row*4+cg, same warp)
        rowmax = fmaxf(rowmax, __shfl_xor_sync(0xffffffffu, rowmax, 1));
        rowmax = fmaxf(rowmax, __shfl_xor_sync(0xffffffffu, rowmax, 2));

        float newm = fmaxf(m, rowmax);
        float corr = __expf(m - newm);     // first iter: exp(-inf - finite) = 0
        float rs = 0.f;
        float p[16];
        #pragma unroll
        for (int c = 0; c < 16; c++) { p[c] = __expf(s[c] - newm); rs += p[c]; }
        rs += __shfl_xor_sync(0xffffffffu, rs, 1);
        rs += __shfl_xor_sync(0xffffffffu, rs, 2);
        l = l * corr + rs;
        m = newm;
        #pragma unroll
        for (int c = 0; c < 16; c++) acc[c] *= corr;
        #pragma unroll
        for (int c = 0; c < 16; c++) Ps[row * AS + c * 4 + cg] = p[c];
        __syncthreads();

        // acc += P @ V  (thread owns head-dims dc = c*4+cg)
        #pragma unroll 4
        for (int j = 0; j < 64; j++) {
            float pj = Ps[row * AS + j];
            #pragma unroll
            for (int c = 0; c < 16; c++)
                acc[c] += pj * Vs[j * AS + c * 4 + cg];
        }
    }

    const float inv = 1.f / l;
    const size_t obase = (size_t)(tb + q0 + row) * HID + (g * HQ + h) * HEADD;
    #pragma unroll
    for (int c = 0; c < 16; c++)
        out[obase + c * 4 + cg] = acc[c] * inv;
}

// ---------------- launcher ----------------
extern "C" void kernel_launch(void* const* d_in, const int* in_sizes, int n_in,
                              void* d_out, int out_size)
{
    const float* hidden = (const float*)d_in[0];
    const float* cosv   = (const float*)d_in[1];
    const float* sinv   = (const float*)d_in[2];
    const float* Wqkv   = (const float*)d_in[3];
    const float* Wdense = (const float*)d_in[4];
    float* out = (float*)d_out;

    float *qkv, *attn;
    cudaGetSymbolAddress((void**)&qkv, g_qkv);
    cudaGetSymbolAddress((void**)&attn, g_attn);

    // 1) QKV projection: [2048,9216] = [2048,8192] @ [8192,9216]
    dim3 g1(QKVW / BN, T_TOK / BM);
    sgemm_kernel<<<g1, 256>>>(T_TOK, QKVW, HID, hidden, Wqkv, qkv);

    // 2) RoPE on q heads + k (in place)
    const int rope_total = T_TOK * GKV * (HQ + 1) * 32;
    rope_kernel<<<(rope_total + 255) / 256, 256>>>(qkv, cosv, sinv);

    // 3) causal GQA flash attention -> g_attn [2048, 8192] (bsghd layout flattened)
    const int attn_smem = 4 * 64 * AS * (int)sizeof(float);   // 69,632 B
    cudaFuncSetAttribute(attn_kernel, cudaFuncAttributeMaxDynamicSharedMemorySize, attn_smem);
    attn_kernel<<<dim3(16, 16, 16), 256, attn_smem>>>(qkv, attn);

    // 4) dense projection: [2048,8192] = [2048,8192] @ [8192,8192]
    dim3 g2(HID / BN, T_TOK / BM);
    sgemm_kernel<<<g2, 256>>>(T_TOK, HID, HID, attn, Wdense, out);
}

// round 3
// speedup vs baseline: 2.7016x; 2.7016x over previous
#include <cuda_runtime.h>
#include <cuda_bf16.h>
#include <math.h>
#include <stdint.h>

// ---------------- problem constants ----------------
#define T_TOK 2048      // BATCH*SEQ
#define HID   8192
#define QKVW  9216      // G*(HQ+2)*HEAD = 8*18*64
#define GKV   8
#define HQ    16
#define HEADD 64
#define SEQ   1024

typedef __nv_bfloat16 bf16;

// ---------------- scratch (__device__ globals; allocation-free rule) ----------------
__device__ __align__(128) float g_qkv[(size_t)T_TOK * QKVW];          // 75.5 MB
__device__ __align__(128) bf16  g_ahi[(size_t)T_TOK * HID];
__device__ __align__(128) bf16  g_alo[(size_t)T_TOK * HID];
__device__ __align__(128) bf16  g_ohi[(size_t)T_TOK * HID];
__device__ __align__(128) bf16  g_olo[(size_t)T_TOK * HID];
__device__ __align__(128) bf16  g_wq_hi[(size_t)QKVW * HID];
__device__ __align__(128) bf16  g_wq_lo[(size_t)QKVW * HID];
__device__ __align__(128) bf16  g_wd_hi[(size_t)HID * HID];
__device__ __align__(128) bf16  g_wd_lo[(size_t)HID * HID];

// ---------------- PTX helpers (portable: compute_103 base target) ----------------
__device__ __forceinline__ uint32_t smem_u32(const void* p) {
    uint32_t a;
    asm("{ .reg .u64 t; cvta.to.shared.u64 t, %1; cvt.u32.u64 %0, t; }" : "=r"(a) : "l"(p));
    return a;
}
#define CPA16(dst, src)   asm volatile("cp.async.cg.shared.global [%0], [%1], 16;" :: "r"(dst), "l"(src))
#define CPA_COMMIT()      asm volatile("cp.async.commit_group;" ::: "memory")
#define CPA_WAIT(n)       asm volatile("cp.async.wait_group %0;" :: "n"(n) : "memory")

__device__ __forceinline__ void ldmat_x4(uint32_t* r, uint32_t addr) {
    asm volatile("ldmatrix.sync.aligned.m8n8.x4.shared.b16 {%0,%1,%2,%3}, [%4];"
        : "=r"(r[0]), "=r"(r[1]), "=r"(r[2]), "=r"(r[3]) : "r"(addr));
}
__device__ __forceinline__ void mma16816(float* d, const uint32_t* a, const uint32_t* b) {
    asm volatile("mma.sync.aligned.m16n8k16.row.col.f32.bf16.bf16.f32 "
        "{%0,%1,%2,%3}, {%4,%5,%6,%7}, {%8,%9}, {%0,%1,%2,%3};"
        : "+f"(d[0]), "+f"(d[1]), "+f"(d[2]), "+f"(d[3])
        : "r"(a[0]), "r"(a[1]), "r"(a[2]), "r"(a[3]), "r"(b[0]), "r"(b[1]));
}
#define SWZ(off) ((off) ^ (((off) >> 3) & 0x70))

// ---------------- fp32 -> (hi, lo) bf16 split ----------------
__global__ __launch_bounds__(256) void split_kernel(
    const float* __restrict__ x, bf16* __restrict__ hi, bf16* __restrict__ lo, int n4)
{
    int i = blockIdx.x * 256 + threadIdx.x;
    if (i >= n4) return;
    float4 v = *(const float4*)(x + (size_t)i * 4);
    bf16 h0 = __float2bfloat16(v.x), h1 = __float2bfloat16(v.y);
    bf16 h2 = __float2bfloat16(v.z), h3 = __float2bfloat16(v.w);
    bf16 l0 = __float2bfloat16(v.x - __bfloat162float(h0));
    bf16 l1 = __float2bfloat16(v.y - __bfloat162float(h1));
    bf16 l2 = __float2bfloat16(v.z - __bfloat162float(h2));
    bf16 l3 = __float2bfloat16(v.w - __bfloat162float(h3));
    *(__nv_bfloat162*)(hi + (size_t)i * 4)     = __nv_bfloat162(h0, h1);
    *(__nv_bfloat162*)(hi + (size_t)i * 4 + 2) = __nv_bfloat162(h2, h3);
    *(__nv_bfloat162*)(lo + (size_t)i * 4)     = __nv_bfloat162(l0, l1);
    *(__nv_bfloat162*)(lo + (size_t)i * 4 + 2) = __nv_bfloat162(l2, l3);
}

// ---------------- W [K,N] fp32 -> (hi, lo) bf16 [N,K] (transpose + split) ----------------
__global__ __launch_bounds__(256) void transpose_split_kernel(
    const float* __restrict__ W, int K, int N, bf16* __restrict__ oh, bf16* __restrict__ ol)
{
    __shared__ float t[32][33];
    const int tx = threadIdx.x, ty = threadIdx.y;     // block (32, 8)
    const int k0 = blockIdx.y * 32, n0 = blockIdx.x * 32;
    #pragma unroll
    for (int j = ty; j < 32; j += 8)
        t[j][tx] = W[(size_t)(k0 + j) * N + n0 + tx];
    __syncthreads();
    #pragma unroll
    for (int j = ty; j < 32; j += 8) {
        float v = t[tx][j];
        bf16 h = __float2bfloat16(v);
        bf16 l = __float2bfloat16(v - __bfloat162float(h));
        oh[(size_t)(n0 + j) * K + k0 + tx] = h;
        ol[(size_t)(n0 + j) * K + k0 + tx] = l;
    }
}

// ---------------- split-bf16 GEMM via mma.sync (HMMA) ----------------
// C[M,N] = A @ B^T;  A as (Ahi,Alo)[M,K] bf16, B as (Bhi,Blo)[N,K] bf16.
// CTA tile 128x128, K-chunk 64, 8 warps (4 over M x 2 over N), warp tile 32x64.
// SMEM stage: Ah | Al | Bh | Bl, each 128 rows x 128 bytes SW128-swizzled.
#define TILE_B 16384
#define STAGE_B 65536
#define GSMEM (2 * STAGE_B)

__global__ __launch_bounds__(256) void gemm_split_mma(
    int M, int N, int K,
    const bf16* __restrict__ Ahi, const bf16* __restrict__ Alo,
    const bf16* __restrict__ Bhi, const bf16* __restrict__ Blo,
    float* __restrict__ C)
{
    extern __shared__ char smem[];
    const uint32_t sb = smem_u32(smem);
    const int tid = threadIdx.x, wid = tid >> 5, lane = tid & 31;
    const int m0 = blockIdx.y * 128, n0 = blockIdx.x * 128;
    const int wm = wid & 3, wn = wid >> 2;

    const bf16* srcs[4] = { Ahi, Alo, Bhi, Blo };
    const int rowbase[4] = { m0, m0, n0, n0 };

    float acc[2][8][4];
    #pragma unroll
    for (int i = 0; i < 2; i++)
        #pragma unroll
        for (int j = 0; j < 8; j++)
            #pragma unroll
            for (int q = 0; q < 4; q++) acc[i][j][q] = 0.f;

    const int nch = K >> 6;     // K / 64

    // ---- issue loads for chunk c into stage st ----
    #define ISSUE(c, st) do {                                                     \
        const uint32_t base_ = sb + (st) * STAGE_B;                               \
        _Pragma("unroll")                                                         \
        for (int t_ = 0; t_ < 4; ++t_) {                                          \
            _Pragma("unroll")                                                     \
            for (int j_ = 0; j_ < 4; ++j_) {                                      \
                const int i_ = tid + j_ * 256;                                    \
                const int r_ = i_ >> 3, ch_ = i_ & 7;                             \
                const uint32_t dst_ = base_ + t_ * TILE_B + SWZ((uint32_t)(r_ * 128 + ch_ * 16)); \
                const bf16* g_ = srcs[t_] + (size_t)(rowbase[t_] + r_) * K + (c) * 64 + ch_ * 8;  \
                CPA16(dst_, g_);                                                  \
            }                                                                     \
        }                                                                         \
        CPA_COMMIT();                                                             \
    } while (0)

    ISSUE(0, 0);

    const int arow = wm * 32 + (lane & 15);
    const int ahalf = lane >> 4;
    const int brow = wn * 64 + ((lane >> 4) << 3) + (lane & 7);
    const int bhalf = (lane >> 3) & 1;

    for (int c = 0; c < nch; ++c) {
        const int st = c & 1;
        if (c + 1 < nch) { ISSUE(c + 1, (c + 1) & 1); CPA_WAIT(1); }
        else             { CPA_WAIT(0); }
        __syncthreads();

        const uint32_t base = sb + st * STAGE_B;
        #pragma unroll
        for (int combo = 0; combo < 3; ++combo) {
            const uint32_t abase = base + (combo == 2 ? TILE_B : 0);
            const uint32_t bbase = base + 2 * TILE_B + (combo == 1 ? TILE_B : 0);
            #pragma unroll
            for (int ks = 0; ks < 4; ++ks) {
                uint32_t a[2][4], b[4][4];
                #pragma unroll
                for (int mt = 0; mt < 2; ++mt)
                    ldmat_x4(a[mt], abase + SWZ((uint32_t)((arow + mt * 16) * 128 + (ks * 2 + ahalf) * 16)));
                #pragma unroll
                for (int nt4 = 0; nt4 < 4; ++nt4)
                    ldmat_x4(b[nt4], bbase + SWZ((uint32_t)((brow + nt4 * 16) * 128 + (ks * 2 + bhalf) * 16)));
                #pragma unroll
                for (int mt = 0; mt < 2; ++mt)
                    #pragma unroll
                    for (int nt = 0; nt < 8; ++nt)
                        mma16816(acc[mt][nt], a[mt], &b[nt >> 1][(nt & 1) * 2]);
            }
        }
        __syncthreads();
    }

    // ---- epilogue: write fragments to C ----
    const int crow = m0 + wm * 32 + (lane >> 2);
    const int ccol = n0 + wn * 64 + (lane & 3) * 2;
    #pragma unroll
    for (int mt = 0; mt < 2; ++mt) {
        #pragma unroll
        for (int nt = 0; nt < 8; ++nt) {
            float* p0 = C + (size_t)(crow + mt * 16) * N + ccol + nt * 8;
            float* p1 = p0 + 8 * (size_t)N;
            *(float2*)p0 = make_float2(acc[mt][nt][0], acc[mt][nt][1]);
            *(float2*)p1 = make_float2(acc[mt][nt][2], acc[mt][nt][3]);
        }
    }
    #undef ISSUE
}

// ---------------- RoPE (in-place on qkv fp32) ----------------
__global__ __launch_bounds__(256) void rope_kernel(
    float* __restrict__ qkv, const float* __restrict__ cosv, const float* __restrict__ sinv)
{
    int idx = blockIdx.x * 256 + threadIdx.x;
    const int total = T_TOK * GKV * (HQ + 1) * 32;
    if (idx >= total) return;
    int pr  = idx & 31;
    int tmp = idx >> 5;
    int hd  = tmp % (HQ + 1);
    tmp    /= (HQ + 1);
    int g   = tmp & 7;
    int t   = tmp >> 3;

    size_t base = (size_t)t * QKVW + g * ((HQ + 2) * HEADD) + hd * HEADD;
    float c = cosv[t * 32 + pr];
    float s = sinv[t * 32 + pr];
    float x1 = qkv[base + pr];
    float x2 = qkv[base + 32 + pr];
    qkv[base + pr]      = x1 * c - x2 * s;
    qkv[base + 32 + pr] = x2 * c + x1 * s;
}

// ---------------- Flash attention (fp32 online softmax) -> bf16 hi/lo ----------------
#define AS 68

__global__ __launch_bounds__(256) void attn_kernel(
    const float* __restrict__ qkv, bf16* __restrict__ ohi, bf16* __restrict__ olo)
{
    extern __shared__ float sm[];
    float* Qs = sm;
    float* Ks = sm + 64 * AS;
    float* Vs = sm + 2 * 64 * AS;
    float* Ps = sm + 3 * 64 * AS;

    const int qb = blockIdx.x;
    const int h  = blockIdx.y;
    const int bg = blockIdx.z;
    const int b  = bg >> 3, g = bg & 7;
    const int tid = threadIdx.x;
    const int row = tid >> 2;
    const int cg  = tid & 3;

    const int tb   = b * SEQ;
    const int qoff = g * ((HQ + 2) * HEADD) + h * HEADD;
    const int koff = g * ((HQ + 2) * HEADD) + HQ * HEADD;
    const int voff = koff + HEADD;
    const int q0   = qb * 64;

    for (int idx = tid; idx < 64 * 64; idx += 256) {
        int r = idx >> 6, c = idx & 63;
        Qs[r * AS + c] = qkv[(size_t)(tb + q0 + r) * QKVW + qoff + c];
    }

    float acc[16];
    #pragma unroll
    for (int i = 0; i < 16; i++) acc[i] = 0.f;
    float m = -INFINITY, l = 0.f;

    for (int jb = 0; jb <= qb; jb++) {
        const int j0 = jb * 64;
        __syncthreads();
        for (int idx = tid; idx < 64 * 64; idx += 256) {
            int r = idx >> 6, c = idx & 63;
            size_t gbase = (size_t)(tb + j0 + r) * QKVW;
            Ks[r * AS + c] = qkv[gbase + koff + c];
            Vs[r * AS + c] = qkv[gbase + voff + c];
        }
        __syncthreads();

        float s[16];
        #pragma unroll
        for (int c = 0; c < 16; c++) s[c] = 0.f;
        #pragma unroll 4
        for (int d4 = 0; d4 < 16; d4++) {
            float4 q4 = *(const float4*)(Qs + row * AS + d4 * 4);
            #pragma unroll
            for (int c = 0; c < 16; c++) {
                float4 k4 = *(const float4*)(Ks + (c * 4 + cg) * AS + d4 * 4);
                s[c] += q4.x * k4.x + q4.y * k4.y + q4.z * k4.z + q4.w * k4.w;
            }
        }

        const float SCALE = 0.125f;
        float rowmax = -INFINITY;
        if (jb == qb) {
            #pragma unroll
            for (int c = 0; c < 16; c++) {
                int kj = j0 + c * 4 + cg;
                s[c] = (kj <= q0 + row) ? s[c] * SCALE : -INFINITY;
                rowmax = fmaxf(rowmax, s[c]);
            }
        } else {
            #pragma unroll
            for (int c = 0; c < 16; c++) {
                s[c] *= SCALE;
                rowmax = fmaxf(rowmax, s[c]);
            }
        }
        rowmax = fmaxf(rowmax, __shfl_xor_sync(0xffffffffu, rowmax, 1));
        rowmax = fmaxf(rowmax, __shfl_xor_sync(0xffffffffu, rowmax, 2));

        float newm = fmaxf(m, rowmax);
        float corr = __expf(m - newm);
        float rs = 0.f;
        float p[16];
        #pragma unroll
        for (int c = 0; c < 16; c++) { p[c] = __expf(s[c] - newm); rs += p[c]; }
        rs += __shfl_xor_sync(0xffffffffu, rs, 1);
        rs += __shfl_xor_sync(0xffffffffu, rs, 2);
        l = l * corr + rs;
        m = newm;
        #pragma unroll
        for (int c = 0; c < 16; c++) acc[c] *= corr;
        #pragma unroll
        for (int c = 0; c < 16; c++) Ps[row * AS + c * 4 + cg] = p[c];
        __syncthreads();

        #pragma unroll 4
        for (int j = 0; j < 64; j++) {
            float pj = Ps[row * AS + j];
            #pragma unroll
            for (int c = 0; c < 16; c++)
                acc[c] += pj * Vs[j * AS + c * 4 + cg];
        }
    }

    const float inv = 1.f / l;
    const size_t obase = (size_t)(tb + q0 + row) * HID + (g * HQ + h) * HEADD;
    #pragma unroll
    for (int c = 0; c < 16; c++) {
        float v = acc[c] * inv;
        bf16 hh = __float2bfloat16(v);
        bf16 ll = __float2bfloat16(v - __bfloat162float(hh));
        ohi[obase + c * 4 + cg] = hh;
        olo[obase + c * 4 + cg] = ll;
    }
}

// ---------------- launcher ----------------
extern "C" void kernel_launch(void* const* d_in, const int* in_sizes, int n_in,
                              void* d_out, int out_size)
{
    const float* hidden = (const float*)d_in[0];
    const float* cosv   = (const float*)d_in[1];
    const float* sinv   = (const float*)d_in[2];
    const float* Wqkv   = (const float*)d_in[3];
    const float* Wdense = (const float*)d_in[4];
    float* out = (float*)d_out;

    float *qkv; bf16 *ahi, *alo, *ohi, *olo, *wqh, *wql, *wdh, *wdl;
    cudaGetSymbolAddress((void**)&qkv, g_qkv);
    cudaGetSymbolAddress((void**)&ahi, g_ahi);
    cudaGetSymbolAddress((void**)&alo, g_alo);
    cudaGetSymbolAddress((void**)&ohi, g_ohi);
    cudaGetSymbolAddress((void**)&olo, g_olo);
    cudaGetSymbolAddress((void**)&wqh, g_wq_hi);
    cudaGetSymbolAddress((void**)&wql, g_wq_lo);
    cudaGetSymbolAddress((void**)&wdh, g_wd_hi);
    cudaGetSymbolAddress((void**)&wdl, g_wd_lo);

    cudaFuncSetAttribute(gemm_split_mma, cudaFuncAttributeMaxDynamicSharedMemorySize, GSMEM);

    // 0) operand conversions
    split_kernel<<<(T_TOK * HID / 4 + 255) / 256, 256>>>(hidden, ahi, alo, T_TOK * HID / 4);
    transpose_split_kernel<<<dim3(QKVW / 32, HID / 32), dim3(32, 8)>>>(Wqkv, HID, QKVW, wqh, wql);
    transpose_split_kernel<<<dim3(HID / 32, HID / 32), dim3(32, 8)>>>(Wdense, HID, HID, wdh, wdl);

    // 1) QKV projection (HMMA): [2048, 9216]
    gemm_split_mma<<<dim3(QKVW / 128, T_TOK / 128), 256, GSMEM>>>(
        T_TOK, QKVW, HID, ahi, alo, wqh, wql, qkv);

    // 2) RoPE
    const int rope_total = T_TOK * GKV * (HQ + 1) * 32;
    rope_kernel<<<(rope_total + 255) / 256, 256>>>(qkv, cosv, sinv);

    // 3) causal GQA flash attention -> bf16 hi/lo
    const int attn_smem = 4 * 64 * AS * (int)sizeof(float);
    cudaFuncSetAttribute(attn_kernel, cudaFuncAttributeMaxDynamicSharedMemorySize, attn_smem);
    attn_kernel<<<dim3(16, 16, 16), 256, attn_smem>>>(qkv, ohi, olo);

    // 4) dense projection (HMMA): [2048, 8192]
    gemm_split_mma<<<dim3(HID / 128, T_TOK / 128), 256, GSMEM>>>(
        T_TOK, HID, HID, ohi, olo, wdh, wdl, out);
}

// round 4
// speedup vs baseline: 3.7105x; 1.3734x over previous
#include <cuda_runtime.h>
#include <cuda_bf16.h>
#include <math.h>
#include <stdint.h>

// ---------------- problem constants ----------------
#define T_TOK 2048      // BATCH*SEQ
#define HID   8192
#define QKVW  9216      // G*(HQ+2)*HEAD = 8*18*64
#define GKV   8
#define HQ    16
#define HEADD 64
#define SEQ   1024

typedef __nv_bfloat16 bf16;

// ---------------- scratch (__device__ globals; allocation-free rule) ----------------
__device__ __align__(128) float g_qkv[(size_t)T_TOK * QKVW];
__device__ __align__(128) bf16  g_ahi[(size_t)T_TOK * HID];
__device__ __align__(128) bf16  g_alo[(size_t)T_TOK * HID];
__device__ __align__(128) bf16  g_ohi[(size_t)T_TOK * HID];
__device__ __align__(128) bf16  g_olo[(size_t)T_TOK * HID];
__device__ __align__(128) bf16  g_wq_hi[(size_t)QKVW * HID];
__device__ __align__(128) bf16  g_wq_lo[(size_t)QKVW * HID];
__device__ __align__(128) bf16  g_wd_hi[(size_t)HID * HID];
__device__ __align__(128) bf16  g_wd_lo[(size_t)HID * HID];
// split QKV for tensor-core attention
__device__ __align__(128) bf16  g_qh[(size_t)T_TOK * GKV * HQ * HEADD];   // 33.5 MB
__device__ __align__(128) bf16  g_ql[(size_t)T_TOK * GKV * HQ * HEADD];
__device__ __align__(128) bf16  g_kh[(size_t)T_TOK * GKV * HEADD];
__device__ __align__(128) bf16  g_kl[(size_t)T_TOK * GKV * HEADD];
__device__ __align__(128) bf16  g_vh[(size_t)T_TOK * GKV * HEADD];
__device__ __align__(128) bf16  g_vl[(size_t)T_TOK * GKV * HEADD];

// ---------------- PTX helpers (portable: compute_103 base target) ----------------
__device__ __forceinline__ uint32_t smem_u32(const void* p) {
    uint32_t a;
    asm("{ .reg .u64 t; cvta.to.shared.u64 t, %1; cvt.u32.u64 %0, t; }" : "=r"(a) : "l"(p));
    return a;
}
#define CPA16(dst, src)   asm volatile("cp.async.cg.shared.global [%0], [%1], 16;" :: "r"(dst), "l"(src))
#define CPA_COMMIT()      asm volatile("cp.async.commit_group;" ::: "memory")
#define CPA_WAIT(n)       asm volatile("cp.async.wait_group %0;" :: "n"(n) : "memory")

__device__ __forceinline__ void ldmat_x4(uint32_t* r, uint32_t addr) {
    asm volatile("ldmatrix.sync.aligned.m8n8.x4.shared.b16 {%0,%1,%2,%3}, [%4];"
        : "=r"(r[0]), "=r"(r[1]), "=r"(r[2]), "=r"(r[3]) : "r"(addr));
}
__device__ __forceinline__ void ldmat_x4_t(uint32_t* r, uint32_t addr) {
    asm volatile("ldmatrix.sync.aligned.m8n8.x4.trans.shared.b16 {%0,%1,%2,%3}, [%4];"
        : "=r"(r[0]), "=r"(r[1]), "=r"(r[2]), "=r"(r[3]) : "r"(addr));
}
__device__ __forceinline__ void mma16816(float* d, const uint32_t* a, const uint32_t* b) {
    asm volatile("mma.sync.aligned.m16n8k16.row.col.f32.bf16.bf16.f32 "
        "{%0,%1,%2,%3}, {%4,%5,%6,%7}, {%8,%9}, {%0,%1,%2,%3};"
        : "+f"(d[0]), "+f"(d[1]), "+f"(d[2]), "+f"(d[3])
        : "r"(a[0]), "r"(a[1]), "r"(a[2]), "r"(a[3]), "r"(b[0]), "r"(b[1]));
}
#define SWZ(off) ((off) ^ (((off) >> 3) & 0x70))

__device__ __forceinline__ uint32_t packbf2(float lo, float hi) {
    __nv_bfloat162 t = __floats2bfloat162_rn(lo, hi);   // .x = lo, .y = hi
    return *(uint32_t*)&t;
}
__device__ __forceinline__ uint32_t residbf2(uint32_t hpk, float lo, float hi) {
    float hlo = __uint_as_float(hpk << 16);
    float hhi = __uint_as_float(hpk & 0xffff0000u);
    return packbf2(lo - hlo, hi - hhi);
}

// ---------------- fp32 -> (hi, lo) bf16 split ----------------
__global__ __launch_bounds__(256) void split_kernel(
    const float* __restrict__ x, bf16* __restrict__ hi, bf16* __restrict__ lo, int n4)
{
    int i = blockIdx.x * 256 + threadIdx.x;
    if (i >= n4) return;
    float4 v = *(const float4*)(x + (size_t)i * 4);
    bf16 h0 = __float2bfloat16(v.x), h1 = __float2bfloat16(v.y);
    bf16 h2 = __float2bfloat16(v.z), h3 = __float2bfloat16(v.w);
    bf16 l0 = __float2bfloat16(v.x - __bfloat162float(h0));
    bf16 l1 = __float2bfloat16(v.y - __bfloat162float(h1));
    bf16 l2 = __float2bfloat16(v.z - __bfloat162float(h2));
    bf16 l3 = __float2bfloat16(v.w - __bfloat162float(h3));
    *(__nv_bfloat162*)(hi + (size_t)i * 4)     = __nv_bfloat162(h0, h1);
    *(__nv_bfloat162*)(hi + (size_t)i * 4 + 2) = __nv_bfloat162(h2, h3);
    *(__nv_bfloat162*)(lo + (size_t)i * 4)     = __nv_bfloat162(l0, l1);
    *(__nv_bfloat162*)(lo + (size_t)i * 4 + 2) = __nv_bfloat162(l2, l3);
}

// ---------------- W [K,N] fp32 -> (hi, lo) bf16 [N,K] (transpose + split) ----------------
__global__ __launch_bounds__(256) void transpose_split_kernel(
    const float* __restrict__ W, int K, int N, bf16* __restrict__ oh, bf16* __restrict__ ol)
{
    __shared__ float t[32][33];
    const int tx = threadIdx.x, ty = threadIdx.y;     // block (32, 8)
    const int k0 = blockIdx.y * 32, n0 = blockIdx.x * 32;
    #pragma unroll
    for (int j = ty; j < 32; j += 8)
        t[j][tx] = W[(size_t)(k0 + j) * N + n0 + tx];
    __syncthreads();
    #pragma unroll
    for (int j = ty; j < 32; j += 8) {
        float v = t[tx][j];
        bf16 h = __float2bfloat16(v);
        bf16 l = __float2bfloat16(v - __bfloat162float(h));
        oh[(size_t)(n0 + j) * K + k0 + tx] = h;
        ol[(size_t)(n0 + j) * K + k0 + tx] = l;
    }
}

// ---------------- split-bf16 GEMM via mma.sync (HMMA) — unchanged (validated) ----------------
#define TILE_B 16384
#define STAGE_B 65536
#define GSMEM (2 * STAGE_B)

__global__ __launch_bounds__(256) void gemm_split_mma(
    int M, int N, int K,
    const bf16* __restrict__ Ahi, const bf16* __restrict__ Alo,
    const bf16* __restrict__ Bhi, const bf16* __restrict__ Blo,
    float* __restrict__ C)
{
    extern __shared__ char smem[];
    const uint32_t sb = smem_u32(smem);
    const int tid = threadIdx.x, wid = tid >> 5, lane = tid & 31;
    const int m0 = blockIdx.y * 128, n0 = blockIdx.x * 128;
    const int wm = wid & 3, wn = wid >> 2;

    const bf16* srcs[4] = { Ahi, Alo, Bhi, Blo };
    const int rowbase[4] = { m0, m0, n0, n0 };

    float acc[2][8][4];
    #pragma unroll
    for (int i = 0; i < 2; i++)
        #pragma unroll
        for (int j = 0; j < 8; j++)
            #pragma unroll
            for (int q = 0; q < 4; q++) acc[i][j][q] = 0.f;

    const int nch = K >> 6;

    #define ISSUE(c, st) do {                                                     \
        const uint32_t base_ = sb + (st) * STAGE_B;                               \
        _Pragma("unroll")                                                         \
        for (int t_ = 0; t_ < 4; ++t_) {                                          \
            _Pragma("unroll")                                                     \
            for (int j_ = 0; j_ < 4; ++j_) {                                      \
                const int i_ = tid + j_ * 256;                                    \
                const int r_ = i_ >> 3, ch_ = i_ & 7;                             \
                const uint32_t dst_ = base_ + t_ * TILE_B + SWZ((uint32_t)(r_ * 128 + ch_ * 16)); \
                const bf16* g_ = srcs[t_] + (size_t)(rowbase[t_] + r_) * K + (c) * 64 + ch_ * 8;  \
                CPA16(dst_, g_);                                                  \
            }                                                                     \
        }                                                                         \
        CPA_COMMIT();                                                             \
    } while (0)

    ISSUE(0, 0);

    const int arow = wm * 32 + (lane & 15);
    const int ahalf = lane >> 4;
    const int brow = wn * 64 + ((lane >> 4) << 3) + (lane & 7);
    const int bhalf = (lane >> 3) & 1;

    for (int c = 0; c < nch; ++c) {
        const int st = c & 1;
        if (c + 1 < nch) { ISSUE(c + 1, (c + 1) & 1); CPA_WAIT(1); }
        else             { CPA_WAIT(0); }
        __syncthreads();

        const uint32_t base = sb + st * STAGE_B;
        #pragma unroll
        for (int combo = 0; combo < 3; ++combo) {
            const uint32_t abase = base + (combo == 2 ? TILE_B : 0);
            const uint32_t bbase = base + 2 * TILE_B + (combo == 1 ? TILE_B : 0);
            #pragma unroll
            for (int ks = 0; ks < 4; ++ks) {
                uint32_t a[2][4], b[4][4];
                #pragma unroll
                for (int mt = 0; mt < 2; ++mt)
                    ldmat_x4(a[mt], abase + SWZ((uint32_t)((arow + mt * 16) * 128 + (ks * 2 + ahalf) * 16)));
                #pragma unroll
                for (int nt4 = 0; nt4 < 4; ++nt4)
                    ldmat_x4(b[nt4], bbase + SWZ((uint32_t)((brow + nt4 * 16) * 128 + (ks * 2 + bhalf) * 16)));
                #pragma unroll
                for (int mt = 0; mt < 2; ++mt)
                    #pragma unroll
                    for (int nt = 0; nt < 8; ++nt)
                        mma16816(acc[mt][nt], a[mt], &b[nt >> 1][(nt & 1) * 2]);
            }
        }
        __syncthreads();
    }

    const int crow = m0 + wm * 32 + (lane >> 2);
    const int ccol = n0 + wn * 64 + (lane & 3) * 2;
    #pragma unroll
    for (int mt = 0; mt < 2; ++mt) {
        #pragma unroll
        for (int nt = 0; nt < 8; ++nt) {
            float* p0 = C + (size_t)(crow + mt * 16) * N + ccol + nt * 8;
            float* p1 = p0 + 8 * (size_t)N;
            *(float2*)p0 = make_float2(acc[mt][nt][0], acc[mt][nt][1]);
            *(float2*)p1 = make_float2(acc[mt][nt][2], acc[mt][nt][3]);
        }
    }
    #undef ISSUE
}

// ---------------- RoPE + split: qkv fp32 -> split-bf16 Q/K/V arrays ----------------
// Q: [t][g][h][d], K/V: [t][g][d]
__global__ __launch_bounds__(256) void rope_split_kernel(
    const float* __restrict__ qkv, const float* __restrict__ cosv, const float* __restrict__ sinv,
    bf16* __restrict__ qh, bf16* __restrict__ ql,
    bf16* __restrict__ kh, bf16* __restrict__ kl,
    bf16* __restrict__ vh, bf16* __restrict__ vl)
{
    int idx = blockIdx.x * 256 + threadIdx.x;
    const int total = T_TOK * GKV * 18 * 32;
    if (idx >= total) return;
    int pr  = idx & 31;
    int tmp = idx >> 5;
    int hd  = tmp % 18;
    tmp    /= 18;
    int g   = tmp & 7;
    int t   = tmp >> 3;

    size_t base = (size_t)t * QKVW + g * (18 * HEADD) + hd * HEADD;
    float x1 = qkv[base + pr];
    float x2 = qkv[base + 32 + pr];
    float y1, y2;
    if (hd < 17) {   // rope on q heads + k
        float c = cosv[t * 32 + pr];
        float s = sinv[t * 32 + pr];
        y1 = x1 * c - x2 * s;
        y2 = x2 * c + x1 * s;
    } else { y1 = x1; y2 = x2; }

    bf16 h1 = __float2bfloat16(y1), h2 = __float2bfloat16(y2);
    bf16 l1 = __float2bfloat16(y1 - __bfloat162float(h1));
    bf16 l2 = __float2bfloat16(y2 - __bfloat162float(h2));

    if (hd < HQ) {
        size_t o = (((size_t)t * GKV + g) * HQ + hd) * HEADD;
        qh[o + pr] = h1; qh[o + 32 + pr] = h2;
        ql[o + pr] = l1; ql[o + 32 + pr] = l2;
    } else if (hd == HQ) {
        size_t o = ((size_t)t * GKV + g) * HEADD;
        kh[o + pr] = h1; kh[o + 32 + pr] = h2;
        kl[o + pr] = l1; kl[o + 32 + pr] = l2;
    } else {
        size_t o = ((size_t)t * GKV + g) * HEADD;
        vh[o + pr] = h1; vh[o + 32 + pr] = h2;
        vl[o + pr] = l1; vl[o + 32 + pr] = l2;
    }
}

// ---------------- HMMA flash attention (split bf16, fp32 softmax) ----------------
// CTA: 128 queries x one (h, b, g). 8 warps, 16 query rows each.
// smem: Qh 16K | Ql 16K | 2 KV stages of {Kh 8K | Kl 8K | Vh 8K | Vl 8K}.
#define BQ 128
#define BKV 64
#define QSMB 32768
#define KVST 32768
#define ATT_SMEM (QSMB + 2 * KVST)

__global__ __launch_bounds__(256) void attn_mma_kernel(
    const bf16* __restrict__ qh, const bf16* __restrict__ ql,
    const bf16* __restrict__ kh, const bf16* __restrict__ kl,
    const bf16* __restrict__ vh, const bf16* __restrict__ vl,
    bf16* __restrict__ ohi, bf16* __restrict__ olo)
{
    extern __shared__ char smem[];
    const uint32_t sb = smem_u32(smem);
    const int qb = blockIdx.x;     // 0..7
    const int h  = blockIdx.y;     // 0..15
    const int bg = blockIdx.z;     // 0..15
    const int b  = bg >> 3, g = bg & 7;
    const int tid = threadIdx.x, wid = tid >> 5, lane = tid & 31;
    const int tb = b * SEQ, q0 = qb * BQ;

    const bf16* kvsrc[4] = { kh, kl, vh, vl };

    // --- Q tiles (hi, lo): 128 rows x 128B each ---
    #pragma unroll
    for (int arr = 0; arr < 2; ++arr) {
        const bf16* src = arr ? ql : qh;
        #pragma unroll
        for (int j = 0; j < 4; ++j) {
            const int i = tid + j * 256;
            const int r = i >> 3, ch = i & 7;
            const uint32_t dst = sb + arr * 16384 + SWZ((uint32_t)(r * 128 + ch * 16));
            const bf16* gp = src + (((size_t)(tb + q0 + r) * GKV + g) * HQ + h) * HEADD + ch * 8;
            CPA16(dst, gp);
        }
    }
    CPA_COMMIT();

    #define ISSUE_KV(jb_, st_) do {                                                   \
        const int j0_ = (jb_) * BKV;                                                  \
        const uint32_t base_ = sb + QSMB + (st_) * KVST;                              \
        _Pragma("unroll")                                                             \
        for (int q_ = 0; q_ < 8; ++q_) {                                              \
            const int i_ = tid + q_ * 256;                                            \
            const int arr_ = i_ >> 9, r_ = (i_ >> 3) & 63, ch_ = i_ & 7;              \
            const bf16* gp_ = kvsrc[arr_] + ((size_t)(tb + j0_ + r_) * GKV + g) * HEADD + ch_ * 8; \
            CPA16(base_ + arr_ * 8192 + SWZ((uint32_t)(r_ * 128 + ch_ * 16)), gp_);   \
        }                                                                             \
        CPA_COMMIT();                                                                 \
    } while (0)

    ISSUE_KV(0, 0);
    CPA_WAIT(1);        // Q group done
    __syncthreads();

    // --- preload Q fragments (constant across KV loop) ---
    uint32_t aqh[4][4], aql[4][4];
    const int arow = wid * 16 + (lane & 15);
    const int ahalf = lane >> 4;
    #pragma unroll
    for (int ks = 0; ks < 4; ++ks) {
        ldmat_x4(aqh[ks], sb + SWZ((uint32_t)(arow * 128 + (ks * 2 + ahalf) * 16)));
        ldmat_x4(aql[ks], sb + 16384 + SWZ((uint32_t)(arow * 128 + (ks * 2 + ahalf) * 16)));
    }

    float acc[8][4];
    #pragma unroll
    for (int i = 0; i < 8; i++)
        #pragma unroll
        for (int q = 0; q < 4; q++) acc[i][q] = 0.f;
    float m0 = -1e30f, m1 = -1e30f, l0 = 0.f, l1 = 0.f;

    const int brow = ((lane >> 4) << 3) + (lane & 7);
    const int bhalf = (lane >> 3) & 1;
    const int jmax = 2 * qb + 1;

    for (int jb = 0; jb <= jmax; ++jb) {
        const int st = jb & 1;
        if (jb < jmax) { ISSUE_KV(jb + 1, (jb + 1) & 1); CPA_WAIT(1); }
        else           { CPA_WAIT(0); }
        __syncthreads();

        const uint32_t kbh = sb + QSMB + st * KVST;
        const uint32_t kbl = kbh + 8192;
        const uint32_t vbh = kbh + 16384;
        const uint32_t vbl = kbh + 24576;

        // --- S = Q K^T (3 split passes; Kh reused for Qh and Ql) ---
        float s[8][4];
        #pragma unroll
        for (int i = 0; i < 8; i++)
            #pragma unroll
            for (int q = 0; q < 4; q++) s[i][q] = 0.f;

        #pragma unroll
        for (int ks = 0; ks < 4; ++ks) {
            #pragma unroll
            for (int g4 = 0; g4 < 4; ++g4) {
                uint32_t bb[4];
                ldmat_x4(bb, kbh + SWZ((uint32_t)((g4 * 16 + brow) * 128 + (ks * 2 + bhalf) * 16)));
                mma16816(s[2 * g4],     aqh[ks], &bb[0]);
                mma16816(s[2 * g4 + 1], aqh[ks], &bb[2]);
                mma16816(s[2 * g4],     aql[ks], &bb[0]);
                mma16816(s[2 * g4 + 1], aql[ks], &bb[2]);
                ldmat_x4(bb, kbl + SWZ((uint32_t)((g4 * 16 + brow) * 128 + (ks * 2 + bhalf) * 16)));
                mma16816(s[2 * g4],     aqh[ks], &bb[0]);
                mma16816(s[2 * g4 + 1], aqh[ks], &bb[2]);
            }
        }

        // --- scale + causal mask ---
        const float SCALE = 0.125f;
        const int j0 = jb * BKV;
        const int r0g = q0 + wid * 16 + (lane >> 2);
        if (jb >= 2 * qb) {   // diagonal tiles
            #pragma unroll
            for (int nt = 0; nt < 8; ++nt) {
                const int kc = j0 + nt * 8 + (lane & 3) * 2;
                #pragma unroll
                for (int q = 0; q < 4; ++q) {
                    const int row = r0g + ((q >> 1) << 3);
                    const int key = kc + (q & 1);
                    s[nt][q] = (key <= row) ? s[nt][q] * SCALE : -1e30f;
                }
            }
        } else {
            #pragma unroll
            for (int nt = 0; nt < 8; ++nt)
                #pragma unroll
                for (int q = 0; q < 4; ++q) s[nt][q] *= SCALE;
        }

        // --- online softmax (per 2 rows per thread) ---
        float rm0 = -1e30f, rm1 = -1e30f;
        #pragma unroll
        for (int nt = 0; nt < 8; ++nt) {
            rm0 = fmaxf(rm0, fmaxf(s[nt][0], s[nt][1]));
            rm1 = fmaxf(rm1, fmaxf(s[nt][2], s[nt][3]));
        }
        rm0 = fmaxf(rm0, __shfl_xor_sync(0xffffffffu, rm0, 1));
        rm0 = fmaxf(rm0, __shfl_xor_sync(0xffffffffu, rm0, 2));
        rm1 = fmaxf(rm1, __shfl_xor_sync(0xffffffffu, rm1, 1));
        rm1 = fmaxf(rm1, __shfl_xor_sync(0xffffffffu, rm1, 2));

        const float nm0 = fmaxf(m0, rm0), nm1 = fmaxf(m1, rm1);
        const float c0 = __expf(m0 - nm0), c1 = __expf(m1 - nm1);
        float rs0 = 0.f, rs1 = 0.f;
        #pragma unroll
        for (int nt = 0; nt < 8; ++nt) {
            s[nt][0] = __expf(s[nt][0] - nm0);
            s[nt][1] = __expf(s[nt][1] - nm0);
            s[nt][2] = __expf(s[nt][2] - nm1);
            s[nt][3] = __expf(s[nt][3] - nm1);
            rs0 += s[nt][0] + s[nt][1];
            rs1 += s[nt][2] + s[nt][3];
        }
        rs0 += __shfl_xor_sync(0xffffffffu, rs0, 1);
        rs0 += __shfl_xor_sync(0xffffffffu, rs0, 2);
        rs1 += __shfl_xor_sync(0xffffffffu, rs1, 1);
        rs1 += __shfl_xor_sync(0xffffffffu, rs1, 2);
        l0 = l0 * c0 + rs0; l1 = l1 * c1 + rs1;
        m0 = nm0; m1 = nm1;
        #pragma unroll
        for (int nt = 0; nt < 8; ++nt) {
            acc[nt][0] *= c0; acc[nt][1] *= c0;
            acc[nt][2] *= c1; acc[nt][3] *= c1;
        }

        // --- P fragments (hi + lo split) ---
        uint32_t ph[4][4], pl[4][4];
        #pragma unroll
        for (int ks = 0; ks < 4; ++ks) {
            ph[ks][0] = packbf2(s[2 * ks][0], s[2 * ks][1]);
            ph[ks][1] = packbf2(s[2 * ks][2], s[2 * ks][3]);
            ph[ks][2] = packbf2(s[2 * ks + 1][0], s[2 * ks + 1][1]);
            ph[ks][3] = packbf2(s[2 * ks + 1][2], s[2 * ks + 1][3]);
            pl[ks][0] = residbf2(ph[ks][0], s[2 * ks][0], s[2 * ks][1]);
            pl[ks][1] = residbf2(ph[ks][1], s[2 * ks][2], s[2 * ks][3]);
            pl[ks][2] = residbf2(ph[ks][2], s[2 * ks + 1][0], s[2 * ks + 1][1]);
            pl[ks][3] = residbf2(ph[ks][3], s[2 * ks + 1][2], s[2 * ks + 1][3]);
        }

        // --- O += P V (3 split passes; Vh reused for Ph and Pl) ---
        const int vrow0 = ((lane >> 3) & 1) * 8 + (lane & 7);
        const int vch   = lane >> 4;
        #pragma unroll
        for (int ks = 0; ks < 4; ++ks) {
            #pragma unroll
            for (int g4 = 0; g4 < 4; ++g4) {
                uint32_t vv[4];
                ldmat_x4_t(vv, vbh + SWZ((uint32_t)((ks * 16 + vrow0) * 128 + (g4 * 2 + vch) * 16)));
                mma16816(acc[2 * g4],     ph[ks], &vv[0]);
                mma16816(acc[2 * g4 + 1], ph[ks], &vv[2]);
                mma16816(acc[2 * g4],     pl[ks], &vv[0]);
                mma16816(acc[2 * g4 + 1], pl[ks], &vv[2]);
                ldmat_x4_t(vv, vbl + SWZ((uint32_t)((ks * 16 + vrow0) * 128 + (g4 * 2 + vch) * 16)));
                mma16816(acc[2 * g4],     ph[ks], &vv[0]);
                mma16816(acc[2 * g4 + 1], ph[ks], &vv[2]);
            }
        }
        __syncthreads();
    }
    #undef ISSUE_KV

    // --- epilogue: normalize, split to bf16 hi/lo for dense GEMM ---
    const float inv0 = 1.f / l0, inv1 = 1.f / l1;
    const int rA = q0 + wid * 16 + (lane >> 2);
    const size_t colbase = (size_t)(g * HQ + h) * HEADD + (lane & 3) * 2;
    #pragma unroll
    for (int half = 0; half < 2; ++half) {
        const int row = rA + half * 8;
        const float inv = half ? inv1 : inv0;
        const size_t base = (size_t)(tb + row) * HID + colbase;
        #pragma unroll
        for (int nt = 0; nt < 8; ++nt) {
            float v0 = acc[nt][half * 2] * inv;
            float v1 = acc[nt][half * 2 + 1] * inv;
            bf16 h0 = __float2bfloat16(v0), h1 = __float2bfloat16(v1);
            bf16 e0 = __float2bfloat16(v0 - __bfloat162float(h0));
            bf16 e1 = __float2bfloat16(v1 - __bfloat162float(h1));
            *(__nv_bfloat162*)(ohi + base + nt * 8) = __nv_bfloat162(h0, h1);
            *(__nv_bfloat162*)(olo + base + nt * 8) = __nv_bfloat162(e0, e1);
        }
    }
}

// ---------------- launcher ----------------
extern "C" void kernel_launch(void* const* d_in, const int* in_sizes, int n_in,
                              void* d_out, int out_size)
{
    const float* hidden = (const float*)d_in[0];
    const float* cosv   = (const float*)d_in[1];
    const float* sinv   = (const float*)d_in[2];
    const float* Wqkv   = (const float*)d_in[3];
    const float* Wdense = (const float*)d_in[4];
    float* out = (float*)d_out;

    float *qkv; bf16 *ahi, *alo, *ohi, *olo, *wqh, *wql, *wdh, *wdl;
    bf16 *qh, *ql, *kh, *kl, *vh, *vl;
    cudaGetSymbolAddress((void**)&qkv, g_qkv);
    cudaGetSymbolAddress((void**)&ahi, g_ahi);
    cudaGetSymbolAddress((void**)&alo, g_alo);
    cudaGetSymbolAddress((void**)&ohi, g_ohi);
    cudaGetSymbolAddress((void**)&olo, g_olo);
    cudaGetSymbolAddress((void**)&wqh, g_wq_hi);
    cudaGetSymbolAddress((void**)&wql, g_wq_lo);
    cudaGetSymbolAddress((void**)&wdh, g_wd_hi);
    cudaGetSymbolAddress((void**)&wdl, g_wd_lo);
    cudaGetSymbolAddress((void**)&qh, g_qh);
    cudaGetSymbolAddress((void**)&ql, g_ql);
    cudaGetSymbolAddress((void**)&kh, g_kh);
    cudaGetSymbolAddress((void**)&kl, g_kl);
    cudaGetSymbolAddress((void**)&vh, g_vh);
    cudaGetSymbolAddress((void**)&vl, g_vl);

    cudaFuncSetAttribute(gemm_split_mma, cudaFuncAttributeMaxDynamicSharedMemorySize, GSMEM);
    cudaFuncSetAttribute(attn_mma_kernel, cudaFuncAttributeMaxDynamicSharedMemorySize, ATT_SMEM);

    // 0) operand conversions
    split_kernel<<<(T_TOK * HID / 4 + 255) / 256, 256>>>(hidden, ahi, alo, T_TOK * HID / 4);
    transpose_split_kernel<<<dim3(QKVW / 32, HID / 32), dim3(32, 8)>>>(Wqkv, HID, QKVW, wqh, wql);
    transpose_split_kernel<<<dim3(HID / 32, HID / 32), dim3(32, 8)>>>(Wdense, HID, HID, wdh, wdl);

    // 1) QKV projection (HMMA)
    gemm_split_mma<<<dim3(QKVW / 128, T_TOK / 128), 256, GSMEM>>>(
        T_TOK, QKVW, HID, ahi, alo, wqh, wql, qkv);

    // 2) RoPE + split to bf16 Q/K/V
    const int rs_total = T_TOK * GKV * 18 * 32;
    rope_split_kernel<<<(rs_total + 255) / 256, 256>>>(qkv, cosv, sinv, qh, ql, kh, kl, vh, vl);

    // 3) HMMA causal GQA flash attention -> bf16 hi/lo
    attn_mma_kernel<<<dim3(SEQ / BQ, HQ, 16), 256, ATT_SMEM>>>(
        qh, ql, kh, kl, vh, vl, ohi, olo);

    // 4) dense projection (HMMA)
    gemm_split_mma<<<dim3(HID / 128, T_TOK / 128), 256, GSMEM>>>(
        T_TOK, HID, HID, ohi, olo, wdh, wdl, out);
}

// round 6
// speedup vs baseline: 4.4058x; 1.1874x over previous
#include <cuda_runtime.h>
#include <cuda_fp16.h>
#include <math.h>
#include <stdint.h>

// ---------------- problem constants ----------------
#define T_TOK 2048      // BATCH*SEQ
#define HID   8192
#define QKVW  9216      // G*(HQ+2)*HEAD = 8*18*64
#define GKV   8
#define HQ    16
#define HEADD 64
#define SEQ   1024

typedef __half h16;

// ---------------- scratch (__device__ globals; allocation-free rule) ----------------
__device__ __align__(128) float g_qkv[(size_t)T_TOK * QKVW];
__device__ __align__(128) h16  g_ahi[(size_t)T_TOK * HID];
__device__ __align__(128) h16  g_alo[(size_t)T_TOK * HID];
__device__ __align__(128) h16  g_o[(size_t)T_TOK * HID];          // attention out (single fp16)
__device__ __align__(128) h16  g_wq_hi[(size_t)QKVW * HID];
__device__ __align__(128) h16  g_wq_lo[(size_t)QKVW * HID];
__device__ __align__(128) h16  g_wd_hi[(size_t)HID * HID];
__device__ __align__(128) h16  g_wd_lo[(size_t)HID * HID];
// split QKV for tensor-core attention
__device__ __align__(128) h16  g_qh[(size_t)T_TOK * GKV * HQ * HEADD];
__device__ __align__(128) h16  g_ql[(size_t)T_TOK * GKV * HQ * HEADD];
__device__ __align__(128) h16  g_kh[(size_t)T_TOK * GKV * HEADD];
__device__ __align__(128) h16  g_kl[(size_t)T_TOK * GKV * HEADD];
__device__ __align__(128) h16  g_vh[(size_t)T_TOK * GKV * HEADD];
__device__ __align__(128) h16  g_vl[(size_t)T_TOK * GKV * HEADD];

// ---------------- PTX helpers (portable: compute_103 base target) ----------------
__device__ __forceinline__ uint32_t smem_u32(const void* p) {
    uint32_t a;
    asm("{ .reg .u64 t; cvta.to.shared.u64 t, %1; cvt.u32.u64 %0, t; }" : "=r"(a) : "l"(p));
    return a;
}
#define CPA16(dst, src)   asm volatile("cp.async.cg.shared.global [%0], [%1], 16;" :: "r"(dst), "l"(src))
#define CPA_COMMIT()      asm volatile("cp.async.commit_group;" ::: "memory")
#define CPA_WAIT(n)       asm volatile("cp.async.wait_group %0;" :: "n"(n) : "memory")

__device__ __forceinline__ void ldmat_x4(uint32_t* r, uint32_t addr) {
    asm volatile("ldmatrix.sync.aligned.m8n8.x4.shared.b16 {%0,%1,%2,%3}, [%4];"
        : "=r"(r[0]), "=r"(r[1]), "=r"(r[2]), "=r"(r[3]) : "r"(addr));
}
__device__ __forceinline__ void ldmat_x4_t(uint32_t* r, uint32_t addr) {
    asm volatile("ldmatrix.sync.aligned.m8n8.x4.trans.shared.b16 {%0,%1,%2,%3}, [%4];"
        : "=r"(r[0]), "=r"(r[1]), "=r"(r[2]), "=r"(r[3]) : "r"(addr));
}
__device__ __forceinline__ void mma16816(float* d, const uint32_t* a, const uint32_t* b) {
    asm volatile("mma.sync.aligned.m16n8k16.row.col.f32.f16.f16.f32 "
        "{%0,%1,%2,%3}, {%4,%5,%6,%7}, {%8,%9}, {%0,%1,%2,%3};"
        : "+f"(d[0]), "+f"(d[1]), "+f"(d[2]), "+f"(d[3])
        : "r"(a[0]), "r"(a[1]), "r"(a[2]), "r"(a[3]), "r"(b[0]), "r"(b[1]));
}
#define SWZ(off) ((off) ^ (((off) >> 3) & 0x70))

__device__ __forceinline__ uint32_t packh2(float a, float b) {
    __half2 t = __floats2half2_rn(a, b);
    return *(uint32_t*)&t;
}
__device__ __forceinline__ uint32_t residh2(uint32_t hp, float a, float b) {
    __half2 t = *(__half2*)&hp;
    return packh2(a - __half2float(t.x), b - __half2float(t.y));
}

// ---------------- fp32 -> (hi, lo) fp16 split ----------------
__global__ __launch_bounds__(256) void split_kernel(
    const float* __restrict__ x, h16* __restrict__ hi, h16* __restrict__ lo, int n4)
{
    int i = blockIdx.x * 256 + threadIdx.x;
    if (i >= n4) return;
    float4 v = *(const float4*)(x + (size_t)i * 4);
    __half2 h01 = __floats2half2_rn(v.x, v.y);
    __half2 h23 = __floats2half2_rn(v.z, v.w);
    __half2 l01 = __floats2half2_rn(v.x - __half2float(h01.x), v.y - __half2float(h01.y));
    __half2 l23 = __floats2half2_rn(v.z - __half2float(h23.x), v.w - __half2float(h23.y));
    *(__half2*)(hi + (size_t)i * 4)     = h01;
    *(__half2*)(hi + (size_t)i * 4 + 2) = h23;
    *(__half2*)(lo + (size_t)i * 4)     = l01;
    *(__half2*)(lo + (size_t)i * 4 + 2) = l23;
}

// ---------------- W [K,N] fp32 -> (hi, lo) fp16 [N,K] (transpose + split) ----------------
__global__ __launch_bounds__(256) void transpose_split_kernel(
    const float* __restrict__ W, int K, int N, h16* __restrict__ oh, h16* __restrict__ ol)
{
    __shared__ float t[32][33];
    const int tx = threadIdx.x, ty = threadIdx.y;     // block (32, 8)
    const int k0 = blockIdx.y * 32, n0 = blockIdx.x * 32;
    #pragma unroll
    for (int j = ty; j < 32; j += 8)
        t[j][tx] = W[(size_t)(k0 + j) * N + n0 + tx];
    __syncthreads();
    #pragma unroll
    for (int j = ty; j < 32; j += 8) {
        float v = t[tx][j];
        h16 h = __float2half_rn(v);
        h16 l = __float2half_rn(v - __half2float(h));
        oh[(size_t)(n0 + j) * K + k0 + tx] = h;
        ol[(size_t)(n0 + j) * K + k0 + tx] = l;
    }
}

// ---------------- split-fp16 GEMM via mma.sync, 3-stage cp.async pipeline ----------------
// THREE=true : 3 passes (Ah Bh, Ah Bl, Al Bh); stage tiles [Ah][Al][Bh][Bl] (64 KB)
// THREE=false: 2 passes (A Bh, A Bl);          stage tiles [A][Bh][Bl]      (48 KB)
#define NSTG 3

template<bool THREE>
__global__ __launch_bounds__(256) void gemm_mma(
    int M, int N, int K,
    const h16* __restrict__ A0, const h16* __restrict__ A1,
    const h16* __restrict__ B0, const h16* __restrict__ B1,
    float* __restrict__ C)
{
    constexpr int NTILE = THREE ? 4 : 3;
    constexpr uint32_t SB = NTILE * 16384;
    extern __shared__ char smem[];
    const uint32_t sb = smem_u32(smem);
    const int tid = threadIdx.x, wid = tid >> 5, lane = tid & 31;
    const int m0 = blockIdx.y * 128, n0 = blockIdx.x * 128;
    const int wm = wid & 3, wn = wid >> 2;

    const h16* srcs4[4] = { A0, A1, B0, B1 };
    const h16* srcs3[3] = { A0, B0, B1 };
    const int rb4[4] = { m0, m0, n0, n0 };
    const int rb3[3] = { m0, n0, n0 };

    float acc[2][8][4];
    #pragma unroll
    for (int i = 0; i < 2; i++)
        #pragma unroll
        for (int j = 0; j < 8; j++)
            #pragma unroll
            for (int q = 0; q < 4; q++) acc[i][j][q] = 0.f;

    const int nch = K >> 6;

    #define ISSUE(c, st) do {                                                         \
        const uint32_t base_ = sb + (uint32_t)(st) * SB;                              \
        _Pragma("unroll")                                                             \
        for (int j_ = 0; j_ < NTILE * 4; ++j_) {                                      \
            const int i_ = tid + j_ * 256;                                            \
            const int t_ = i_ >> 10, r_ = (i_ >> 3) & 127, ch_ = i_ & 7;              \
            const uint32_t dst_ = base_ + t_ * 16384 + SWZ((uint32_t)(r_ * 128 + ch_ * 16)); \
            const h16* g_ = (THREE ? srcs4[t_] : srcs3[t_])                           \
                + (size_t)((THREE ? rb4[t_] : rb3[t_]) + r_) * K + (c) * 64 + ch_ * 8; \
            CPA16(dst_, g_);                                                          \
        }                                                                             \
        CPA_COMMIT();                                                                 \
    } while (0)

    ISSUE(0, 0);
    if (nch > 1) ISSUE(1, 1);

    const int arow = wm * 32 + (lane & 15);
    const int ahalf = lane >> 4;
    const int brow = wn * 64 + ((lane >> 4) << 3) + (lane & 7);
    const int bhalf = (lane >> 3) & 1;

    for (int c = 0; c < nch; ++c) {
        const int st = c % NSTG;
        if (c + 2 < nch) { ISSUE(c + 2, (c + 2) % NSTG); CPA_WAIT(2); }
        else if (c + 1 < nch) { CPA_WAIT(1); }
        else { CPA_WAIT(0); }
        __syncthreads();

        const uint32_t base = sb + (uint32_t)st * SB;
        constexpr int NCOMBO = THREE ? 3 : 2;
        #pragma unroll
        for (int combo = 0; combo < NCOMBO; ++combo) {
            const uint32_t abase = base + ((THREE && combo == 2) ? 16384 : 0);
            const uint32_t bbase = base + (THREE ? 32768 : 16384) + (combo == 1 ? 16384 : 0);
            #pragma unroll
            for (int ks = 0; ks < 4; ++ks) {
                uint32_t a[2][4], b[4][4];
                #pragma unroll
                for (int mt = 0; mt < 2; ++mt)
                    ldmat_x4(a[mt], abase + SWZ((uint32_t)((arow + mt * 16) * 128 + (ks * 2 + ahalf) * 16)));
                #pragma unroll
                for (int nt4 = 0; nt4 < 4; ++nt4)
                    ldmat_x4(b[nt4], bbase + SWZ((uint32_t)((brow + nt4 * 16) * 128 + (ks * 2 + bhalf) * 16)));
                #pragma unroll
                for (int mt = 0; mt < 2; ++mt)
                    #pragma unroll
                    for (int nt = 0; nt < 8; ++nt)
                        mma16816(acc[mt][nt], a[mt], &b[nt >> 1][(nt & 1) * 2]);
            }
        }
        __syncthreads();
    }

    const int crow = m0 + wm * 32 + (lane >> 2);
    const int ccol = n0 + wn * 64 + (lane & 3) * 2;
    #pragma unroll
    for (int mt = 0; mt < 2; ++mt) {
        #pragma unroll
        for (int nt = 0; nt < 8; ++nt) {
            float* p0 = C + (size_t)(crow + mt * 16) * N + ccol + nt * 8;
            float* p1 = p0 + 8 * (size_t)N;
            *(float2*)p0 = make_float2(acc[mt][nt][0], acc[mt][nt][1]);
            *(float2*)p1 = make_float2(acc[mt][nt][2], acc[mt][nt][3]);
        }
    }
    #undef ISSUE
}

// ---------------- RoPE + split: qkv fp32 -> split-fp16 Q/K/V arrays ----------------
__global__ __launch_bounds__(256) void rope_split_kernel(
    const float* __restrict__ qkv, const float* __restrict__ cosv, const float* __restrict__ sinv,
    h16* __restrict__ qh, h16* __restrict__ ql,
    h16* __restrict__ kh, h16* __restrict__ kl,
    h16* __restrict__ vh, h16* __restrict__ vl)
{
    int idx = blockIdx.x * 256 + threadIdx.x;
    const int total = T_TOK * GKV * 18 * 32;
    if (idx >= total) return;
    int pr  = idx & 31;
    int tmp = idx >> 5;
    int hd  = tmp % 18;
    tmp    /= 18;
    int g   = tmp & 7;
    int t   = tmp >> 3;

    size_t base = (size_t)t * QKVW + g * (18 * HEADD) + hd * HEADD;
    float x1 = qkv[base + pr];
    float x2 = qkv[base + 32 + pr];
    float y1, y2;
    if (hd < 17) {
        float c = cosv[t * 32 + pr];
        float s = sinv[t * 32 + pr];
        y1 = x1 * c - x2 * s;
        y2 = x2 * c + x1 * s;
    } else { y1 = x1; y2 = x2; }

    h16 h1 = __float2half_rn(y1), h2 = __float2half_rn(y2);
    h16 l1 = __float2half_rn(y1 - __half2float(h1));
    h16 l2 = __float2half_rn(y2 - __half2float(h2));

    if (hd < HQ) {
        size_t o = (((size_t)t * GKV + g) * HQ + hd) * HEADD;
        qh[o + pr] = h1; qh[o + 32 + pr] = h2;
        ql[o + pr] = l1; ql[o + 32 + pr] = l2;
    } else if (hd == HQ) {
        size_t o = ((size_t)t * GKV + g) * HEADD;
        kh[o + pr] = h1; kh[o + 32 + pr] = h2;
        kl[o + pr] = l1; kl[o + 32 + pr] = l2;
    } else {
        size_t o = ((size_t)t * GKV + g) * HEADD;
        vh[o + pr] = h1; vh[o + 32 + pr] = h2;
        vl[o + pr] = l1; vl[o + 32 + pr] = l2;
    }
}

// ---------------- HMMA flash attention (split fp16, fp32 softmax) ----------------
#define BQ 128
#define BKV 64
#define QSMB 32768
#define KVST 32768
#define ATT_SMEM (QSMB + 2 * KVST)

__global__ __launch_bounds__(256) void attn_mma_kernel(
    const h16* __restrict__ qh, const h16* __restrict__ ql,
    const h16* __restrict__ kh, const h16* __restrict__ kl,
    const h16* __restrict__ vh, const h16* __restrict__ vl,
    h16* __restrict__ outo)
{
    extern __shared__ char smem[];
    const uint32_t sb = smem_u32(smem);
    const int qb = blockIdx.x;
    const int h  = blockIdx.y;
    const int bg = blockIdx.z;
    const int b  = bg >> 3, g = bg & 7;
    const int tid = threadIdx.x, wid = tid >> 5, lane = tid & 31;
    const int tb = b * SEQ, q0 = qb * BQ;

    const h16* kvsrc[4] = { kh, kl, vh, vl };

    #pragma unroll
    for (int arr = 0; arr < 2; ++arr) {
        const h16* src = arr ? ql : qh;
        #pragma unroll
        for (int j = 0; j < 4; ++j) {
            const int i = tid + j * 256;
            const int r = i >> 3, ch = i & 7;
            const uint32_t dst = sb + arr * 16384 + SWZ((uint32_t)(r * 128 + ch * 16));
            const h16* gp = src + (((size_t)(tb + q0 + r) * GKV + g) * HQ + h) * HEADD + ch * 8;
            CPA16(dst, gp);
        }
    }
    CPA_COMMIT();

    #define ISSUE_KV(jb_, st_) do {                                                   \
        const int j0_ = (jb_) * BKV;                                                  \
        const uint32_t base_ = sb + QSMB + (st_) * KVST;                              \
        _Pragma("unroll")                                                             \
        for (int q_ = 0; q_ < 8; ++q_) {                                              \
            const int i_ = tid + q_ * 256;                                            \
            const int arr_ = i_ >> 9, r_ = (i_ >> 3) & 63, ch_ = i_ & 7;              \
            const h16* gp_ = kvsrc[arr_] + ((size_t)(tb + j0_ + r_) * GKV + g) * HEADD + ch_ * 8; \
            CPA16(base_ + arr_ * 8192 + SWZ((uint32_t)(r_ * 128 + ch_ * 16)), gp_);   \
        }                                                                             \
        CPA_COMMIT();                                                                 \
    } while (0)

    ISSUE_KV(0, 0);
    CPA_WAIT(1);
    __syncthreads();

    uint32_t aqh[4][4], aql[4][4];
    const int arow = wid * 16 + (lane & 15);
    const int ahalf = lane >> 4;
    #pragma unroll
    for (int ks = 0; ks < 4; ++ks) {
        ldmat_x4(aqh[ks], sb + SWZ((uint32_t)(arow * 128 + (ks * 2 + ahalf) * 16)));
        ldmat_x4(aql[ks], sb + 16384 + SWZ((uint32_t)(arow * 128 + (ks * 2 + ahalf) * 16)));
    }

    float acc[8][4];
    #pragma unroll
    for (int i = 0; i < 8; i++)
        #pragma unroll
        for (int q = 0; q < 4; q++) acc[i][q] = 0.f;
    float m0 = -1e30f, m1 = -1e30f, l0 = 0.f, l1 = 0.f;

    const int brow = ((lane >> 4) << 3) + (lane & 7);
    const int bhalf = (lane >> 3) & 1;
    const int jmax = 2 * qb + 1;

    for (int jb = 0; jb <= jmax; ++jb) {
        const int st = jb & 1;
        if (jb < jmax) { ISSUE_KV(jb + 1, (jb + 1) & 1); CPA_WAIT(1); }
        else           { CPA_WAIT(0); }
        __syncthreads();

        const uint32_t kbh = sb + QSMB + st * KVST;
        const uint32_t kbl = kbh + 8192;
        const uint32_t vbh = kbh + 16384;
        const uint32_t vbl = kbh + 24576;

        float s[8][4];
        #pragma unroll
        for (int i = 0; i < 8; i++)
            #pragma unroll
            for (int q = 0; q < 4; q++) s[i][q] = 0.f;

        #pragma unroll
        for (int ks = 0; ks < 4; ++ks) {
            #pragma unroll
            for (int g4 = 0; g4 < 4; ++g4) {
                uint32_t bb[4];
                ldmat_x4(bb, kbh + SWZ((uint32_t)((g4 * 16 + brow) * 128 + (ks * 2 + bhalf) * 16)));
                mma16816(s[2 * g4],     aqh[ks], &bb[0]);
                mma16816(s[2 * g4 + 1], aqh[ks], &bb[2]);
                mma16816(s[2 * g4],     aql[ks], &bb[0]);
                mma16816(s[2 * g4 + 1], aql[ks], &bb[2]);
                ldmat_x4(bb, kbl + SWZ((uint32_t)((g4 * 16 + brow) * 128 + (ks * 2 + bhalf) * 16)));
                mma16816(s[2 * g4],     aqh[ks], &bb[0]);
                mma16816(s[2 * g4 + 1], aqh[ks], &bb[2]);
            }
        }

        const float SCALE = 0.125f;
        const int j0 = jb * BKV;
        const int r0g = q0 + wid * 16 + (lane >> 2);
        if (jb >= 2 * qb) {
            #pragma unroll
            for (int nt = 0; nt < 8; ++nt) {
                const int kc = j0 + nt * 8 + (lane & 3) * 2;
                #pragma unroll
                for (int q = 0; q < 4; ++q) {
                    const int row = r0g + ((q >> 1) << 3);
                    const int key = kc + (q & 1);
                    s[nt][q] = (key <= row) ? s[nt][q] * SCALE : -1e30f;
                }
            }
        } else {
            #pragma unroll
            for (int nt = 0; nt < 8; ++nt)
                #pragma unroll
                for (int q = 0; q < 4; ++q) s[nt][q] *= SCALE;
        }

        float rm0 = -1e30f, rm1 = -1e30f;
        #pragma unroll
        for (int nt = 0; nt < 8; ++nt) {
            rm0 = fmaxf(rm0, fmaxf(s[nt][0], s[nt][1]));
            rm1 = fmaxf(rm1, fmaxf(s[nt][2], s[nt][3]));
        }
        rm0 = fmaxf(rm0, __shfl_xor_sync(0xffffffffu, rm0, 1));
        rm0 = fmaxf(rm0, __shfl_xor_sync(0xffffffffu, rm0, 2));
        rm1 = fmaxf(rm1, __shfl_xor_sync(0xffffffffu, rm1, 1));
        rm1 = fmaxf(rm1, __shfl_xor_sync(0xffffffffu, rm1, 2));

        const float nm0 = fmaxf(m0, rm0), nm1 = fmaxf(m1, rm1);
        const float c0 = __expf(m0 - nm0), c1 = __expf(m1 - nm1);
        float rs0 = 0.f, rs1 = 0.f;
        #pragma unroll
        for (int nt = 0; nt < 8; ++nt) {
            s[nt][0] = __expf(s[nt][0] - nm0);
            s[nt][1] = __expf(s[nt][1] - nm0);
            s[nt][2] = __expf(s[nt][2] - nm1);
            s[nt][3] = __expf(s[nt][3] - nm1);
            rs0 += s[nt][0] + s[nt][1];
            rs1 += s[nt][2] + s[nt][3];
        }
        rs0 += __shfl_xor_sync(0xffffffffu, rs0, 1);
        rs0 += __shfl_xor_sync(0xffffffffu, rs0, 2);
        rs1 += __shfl_xor_sync(0xffffffffu, rs1, 1);
        rs1 += __shfl_xor_sync(0xffffffffu, rs1, 2);
        l0 = l0 * c0 + rs0; l1 = l1 * c1 + rs1;
        m0 = nm0; m1 = nm1;
        #pragma unroll
        for (int nt = 0; nt < 8; ++nt) {
            acc[nt][0] *= c0; acc[nt][1] *= c0;
            acc[nt][2] *= c1; acc[nt][3] *= c1;
        }

        uint32_t ph[4][4], pl[4][4];
        #pragma unroll
        for (int ks = 0; ks < 4; ++ks) {
            ph[ks][0] = packh2(s[2 * ks][0], s[2 * ks][1]);
            ph[ks][1] = packh2(s[2 * ks][2], s[2 * ks][3]);
            ph[ks][2] = packh2(s[2 * ks + 1][0], s[2 * ks + 1][1]);
            ph[ks][3] = packh2(s[2 * ks + 1][2], s[2 * ks + 1][3]);
            pl[ks][0] = residh2(ph[ks][0], s[2 * ks][0], s[2 * ks][1]);
            pl[ks][1] = residh2(ph[ks][1], s[2 * ks][2], s[2 * ks][3]);
            pl[ks][2] = residh2(ph[ks][2], s[2 * ks + 1][0], s[2 * ks + 1][1]);
            pl[ks][3] = residh2(ph[ks][3], s[2 * ks + 1][2], s[2 * ks + 1][3]);
        }

        const int vrow0 = ((lane >> 3) & 1) * 8 + (lane & 7);
        const int vch   = lane >> 4;
        #pragma unroll
        for (int ks = 0; ks < 4; ++ks) {
            #pragma unroll
            for (int g4 = 0; g4 < 4; ++g4) {
                uint32_t vv[4];
                ldmat_x4_t(vv, vbh + SWZ((uint32_t)((ks * 16 + vrow0) * 128 + (g4 * 2 + vch) * 16)));
                mma16816(acc[2 * g4],     ph[ks], &vv[0]);
                mma16816(acc[2 * g4 + 1], ph[ks], &vv[2]);
                mma16816(acc[2 * g4],     pl[ks], &vv[0]);
                mma16816(acc[2 * g4 + 1], pl[ks], &vv[2]);
                ldmat_x4_t(vv, vbl + SWZ((uint32_t)((ks * 16 + vrow0) * 128 + (g4 * 2 + vch) * 16)));
                mma16816(acc[2 * g4],     ph[ks], &vv[0]);
                mma16816(acc[2 * g4 + 1], ph[ks], &vv[2]);
            }
        }
        __syncthreads();
    }
    #undef ISSUE_KV

    // --- epilogue: normalize, single fp16 output for dense GEMM ---
    const float inv0 = 1.f / l0, inv1 = 1.f / l1;
    const int rA = q0 + wid * 16 + (lane >> 2);
    const size_t colbase = (size_t)(g * HQ + h) * HEADD + (lane & 3) * 2;
    #pragma unroll
    for (int half = 0; half < 2; ++half) {
        const int row = rA + half * 8;
        const float inv = half ? inv1 : inv0;
        const size_t base = (size_t)(tb + row) * HID + colbase;
        #pragma unroll
        for (int nt = 0; nt < 8; ++nt) {
            float v0 = acc[nt][half * 2] * inv;
            float v1 = acc[nt][half * 2 + 1] * inv;
            *(__half2*)(outo + base + nt * 8) = __floats2half2_rn(v0, v1);
        }
    }
}

// ---------------- launcher ----------------
extern "C" void kernel_launch(void* const* d_in, const int* in_sizes, int n_in,
                              void* d_out, int out_size)
{
    const float* hidden = (const float*)d_in[0];
    const float* cosv   = (const float*)d_in[1];
    const float* sinv   = (const float*)d_in[2];
    const float* Wqkv   = (const float*)d_in[3];
    const float* Wdense = (const float*)d_in[4];
    float* out = (float*)d_out;

    float *qkv; h16 *ahi, *alo, *oatt, *wqh, *wql, *wdh, *wdl;
    h16 *qh, *ql, *kh, *kl, *vh, *vl;
    cudaGetSymbolAddress((void**)&qkv, g_qkv);
    cudaGetSymbolAddress((void**)&ahi, g_ahi);
    cudaGetSymbolAddress((void**)&alo, g_alo);
    cudaGetSymbolAddress((void**)&oatt, g_o);
    cudaGetSymbolAddress((void**)&wqh, g_wq_hi);
    cudaGetSymbolAddress((void**)&wql, g_wq_lo);
    cudaGetSymbolAddress((void**)&wdh, g_wd_hi);
    cudaGetSymbolAddress((void**)&wdl, g_wd_lo);
    cudaGetSymbolAddress((void**)&qh, g_qh);
    cudaGetSymbolAddress((void**)&ql, g_ql);
    cudaGetSymbolAddress((void**)&kh, g_kh);
    cudaGetSymbolAddress((void**)&kl, g_kl);
    cudaGetSymbolAddress((void**)&vh, g_vh);
    cudaGetSymbolAddress((void**)&vl, g_vl);

    const int smem3 = NSTG * 4 * 16384;   // 196608
    const int smem2 = NSTG * 3 * 16384;   // 147456
    cudaFuncSetAttribute(gemm_mma<true>,  cudaFuncAttributeMaxDynamicSharedMemorySize, smem3);
    cudaFuncSetAttribute(gemm_mma<false>, cudaFuncAttributeMaxDynamicSharedMemorySize, smem2);
    cudaFuncSetAttribute(attn_mma_kernel, cudaFuncAttributeMaxDynamicSharedMemorySize, ATT_SMEM);

    // 0) operand conversions
    split_kernel<<<(T_TOK * HID / 4 + 255) / 256, 256>>>(hidden, ahi, alo, T_TOK * HID / 4);
    transpose_split_kernel<<<dim3(QKVW / 32, HID / 32), dim3(32, 8)>>>(Wqkv, HID, QKVW, wqh, wql);
    transpose_split_kernel<<<dim3(HID / 32, HID / 32), dim3(32, 8)>>>(Wdense, HID, HID, wdh, wdl);

    // 1) QKV projection: 3-pass split fp16 (precision-critical: feeds logits)
    gemm_mma<true><<<dim3(QKVW / 128, T_TOK / 128), 256, smem3>>>(
        T_TOK, QKVW, HID, ahi, alo, wqh, wql, qkv);

    // 2) RoPE + split to fp16 Q/K/V
    const int rs_total = T_TOK * GKV * 18 * 32;
    rope_split_kernel<<<(rs_total + 255) / 256, 256>>>(qkv, cosv, sinv, qh, ql, kh, kl, vh, vl);

    // 3) HMMA causal GQA flash attention -> single fp16
    attn_mma_kernel<<<dim3(SEQ / BQ, HQ, 16), 256, ATT_SMEM>>>(
        qh, ql, kh, kl, vh, vl, oatt);

    // 4) dense projection: 2-pass (A single fp16, W split) — error not amplified
    gemm_mma<false><<<dim3(HID / 128, T_TOK / 128), 256, smem2>>>(
        T_TOK, HID, HID, oatt, oatt, wdh, wdl, out);
}